// round 12
// baseline (speedup 1.0000x reference)
#include <cuda_runtime.h>

#define DIM 128
#define DIM4 (DIM / 4)          // 32 float4 per row
#define NODES_MAX 50000
#define NRELS_MAX 1000
#define PAD 96                  // max combined degree (Poisson(25); >=8 sigma)
#define NSTATB 1024
#define BN_EPS 1e-5f

// Packed adjacency entry: bits[0:16)=neighbor, bits[16:26)=rel, bit31=out-flag
#define PACK_IN(nb, rl)  ((unsigned)(nb) | ((unsigned)(rl) << 16))
#define PACK_OUT(nb, rl) ((unsigned)(nb) | ((unsigned)(rl) << 16) | 0x80000000u)

// Scratch (static device globals — allowed; no runtime allocation)
__device__ float    g_rsc[NRELS_MAX * DIM];    // r * kernels
__device__ float    g_psum[DIM * NSTATB];      // transposed: [d][b]
__device__ float    g_psq[DIM * NSTATB];
__device__ float    g_ca[DIM];                 // fused affine scale
__device__ float    g_cb[DIM];                 // fused affine shift
__device__ int      g_cnt[NODES_MAX];
__device__ unsigned g_lst[NODES_MAX * PAD];    // packed entries (4 B each)

// ---------------------------------------------------------------------------
// inv_du from the reference's degenerate degree loop (6 scalars)
// ---------------------------------------------------------------------------
__device__ __forceinline__ float inv_du_of(int n, int h0, int h2, int r0,
                                           int r2, int t0, int t2) {
    float du = 1.f;
    if (h0 != h2) du += (float)((n == h0) + (n == h2));
    if (r0 != r2) du += (float)((n == r0) + (n == r2));
    if (t0 != t2) du += (float)((n == t0) + (n == t2));
    return 1.0f / du;
}

// ---------------------------------------------------------------------------
// K1: per-block partial column sums (reads coalesced; 2 scattered stores)
// ---------------------------------------------------------------------------
__global__ void k_stats(const float* __restrict__ x, int e) {
    int d = threadIdx.x;            // 0..127
    int b = blockIdx.x;             // 0..NSTATB-1
    float s = 0.f, ss = 0.f;
    for (int row = b; row < e; row += NSTATB) {
        float v = x[(size_t)row * DIM + d];
        s += v;
        ss += v * v;
    }
    g_psum[d * NSTATB + b] = s;
    g_psq[d * NSTATB + b] = ss;
}

// ---------------------------------------------------------------------------
// K2: parallel reduce, coalesced reads (thread t reads [d*NSTATB + t])
// ---------------------------------------------------------------------------
__global__ void __launch_bounds__(256) k_coef(
        const float* __restrict__ gamma,
        const float* __restrict__ beta,
        const float* __restrict__ kern, int e) {
    __shared__ double sh_s[256];
    __shared__ double sh_q[256];
    int d = blockIdx.x;             // 0..127 feature index
    int t = threadIdx.x;            // 0..255

    double s = 0.0, ss = 0.0;
    #pragma unroll
    for (int b = t; b < NSTATB; b += 256) {
        s  += (double)g_psum[d * NSTATB + b];
        ss += (double)g_psq[d * NSTATB + b];
    }
    sh_s[t] = s;
    sh_q[t] = ss;
    __syncthreads();
    for (int o = 128; o > 0; o >>= 1) {
        if (t < o) {
            sh_s[t] += sh_s[t + o];
            sh_q[t] += sh_q[t + o];
        }
        __syncthreads();
    }
    if (t == 0) {
        double mean_d = sh_s[0] / (double)e;
        double var_d  = sh_q[0] / (double)e - mean_d * mean_d;  // biased var
        float mean = (float)mean_d;
        float inv = rsqrtf((float)var_d + BN_EPS);
        float g = gamma[d], k = kern[d];
        g_ca[d] = inv * g * k;
        g_cb[d] = (beta[d] - mean * inv * g) * k;
    }
}

// ---------------------------------------------------------------------------
// K3: r * kernels
// ---------------------------------------------------------------------------
__global__ void k_rsc(const float* __restrict__ r,
                      const float* __restrict__ kern, int total) {
    int i = blockIdx.x * blockDim.x + threadIdx.x;
    if (i < total) g_rsc[i] = r[i] * kern[i & (DIM - 1)];
}

// ---------------------------------------------------------------------------
// Adjacency build: zero counters, then single-pass padded-bucket fill
// with PACKED 4-byte entries (halves scatter footprint vs int2).
// ---------------------------------------------------------------------------
__global__ void k_zero(int e) {
    int i = blockIdx.x * blockDim.x + threadIdx.x;
    if (i < e) g_cnt[i] = 0;
}

__global__ void k_fill(const int* __restrict__ heads,
                       const int* __restrict__ tails,
                       const int* __restrict__ rels, int E) {
    int i = blockIdx.x * blockDim.x + threadIdx.x;
    if (i >= E) return;
    int h = heads[i], t = tails[i], rl = rels[i];
    int p = atomicAdd(&g_cnt[t], 1);
    if (p < PAD) g_lst[t * PAD + p] = PACK_IN(h, rl);
    int q = atomicAdd(&g_cnt[h], 1);
    if (q < PAD) g_lst[h * PAD + q] = PACK_OUT(t, rl);
}

// ---------------------------------------------------------------------------
// acc += (v*a + b) + sgn * w
// ---------------------------------------------------------------------------
__device__ __forceinline__ void acc_term(float4& acc, float4 v, float4 w,
                                         float4 a, float4 b, float sgn) {
    acc.x += fmaf(sgn, w.x, fmaf(v.x, a.x, b.x));
    acc.y += fmaf(sgn, w.y, fmaf(v.y, a.y, b.y));
    acc.z += fmaf(sgn, w.z, fmaf(v.z, a.z, b.z));
    acc.w += fmaf(sgn, w.w, fmaf(v.w, a.w, b.w));
}

// ---------------------------------------------------------------------------
// K4: pull-gather over the packed list. One warp per node; ONE shfl per
// term (packed entry), 4-deep unrolled gathers, one deterministic STG.
// ---------------------------------------------------------------------------
__global__ void __launch_bounds__(256) k_gather(
        const float* __restrict__ x,
        const int* __restrict__ heads,
        const int* __restrict__ tails,
        const int* __restrict__ rels,
        float* __restrict__ out, int e) {
    int n = (blockIdx.x * blockDim.x + threadIdx.x) >> 5;
    if (n >= e) return;
    int lane = threadIdx.x & 31;

    const float4* x4  = reinterpret_cast<const float4*>(x);
    const float4* rs4 = reinterpret_cast<const float4*>(g_rsc);
    float4 a = reinterpret_cast<const float4*>(g_ca)[lane];
    float4 b = reinterpret_cast<const float4*>(g_cb)[lane];

    // seed: own normalized row
    float4 v = x4[(size_t)n * DIM4 + lane];
    float4 acc0, acc1, acc2, acc3;
    acc0.x = fmaf(v.x, a.x, b.x);
    acc0.y = fmaf(v.y, a.y, b.y);
    acc0.z = fmaf(v.z, a.z, b.z);
    acc0.w = fmaf(v.w, a.w, b.w);
    acc1 = make_float4(0.f, 0.f, 0.f, 0.f);
    acc2 = acc1; acc3 = acc1;

    int cnt = min(g_cnt[n], PAD);
    const unsigned* list = g_lst + (size_t)n * PAD;

    for (int base = 0; base < cnt; base += 32) {
        int idx = base + lane;
        unsigned pr = (idx < cnt) ? list[idx] : 0u;
        int m = min(32, cnt - base);
        int j = 0;
        for (; j + 3 < m; j += 4) {
            unsigned y0 = __shfl_sync(0xffffffffu, pr, j);
            unsigned y1 = __shfl_sync(0xffffffffu, pr, j + 1);
            unsigned y2 = __shfl_sync(0xffffffffu, pr, j + 2);
            unsigned y3 = __shfl_sync(0xffffffffu, pr, j + 3);
            int n0 = y0 & 0xffff, r0 = (y0 >> 16) & 0x3ff;
            int n1 = y1 & 0xffff, r1 = (y1 >> 16) & 0x3ff;
            int n2 = y2 & 0xffff, r2 = (y2 >> 16) & 0x3ff;
            int n3 = y3 & 0xffff, r3 = (y3 >> 16) & 0x3ff;
            // 8 independent 16B loads in flight
            float4 v0 = __ldg(&x4[(size_t)n0 * DIM4 + lane]);
            float4 v1 = __ldg(&x4[(size_t)n1 * DIM4 + lane]);
            float4 v2 = __ldg(&x4[(size_t)n2 * DIM4 + lane]);
            float4 v3 = __ldg(&x4[(size_t)n3 * DIM4 + lane]);
            float4 w0 = __ldg(&rs4[(size_t)r0 * DIM4 + lane]);
            float4 w1 = __ldg(&rs4[(size_t)r1 * DIM4 + lane]);
            float4 w2 = __ldg(&rs4[(size_t)r2 * DIM4 + lane]);
            float4 w3 = __ldg(&rs4[(size_t)r3 * DIM4 + lane]);
            acc_term(acc0, v0, w0, a, b, ((int)y0 < 0) ? -1.f : 1.f);
            acc_term(acc1, v1, w1, a, b, ((int)y1 < 0) ? -1.f : 1.f);
            acc_term(acc2, v2, w2, a, b, ((int)y2 < 0) ? -1.f : 1.f);
            acc_term(acc3, v3, w3, a, b, ((int)y3 < 0) ? -1.f : 1.f);
        }
        for (; j < m; j++) {
            unsigned y0 = __shfl_sync(0xffffffffu, pr, j);
            int n0 = y0 & 0xffff, r0 = (y0 >> 16) & 0x3ff;
            float4 v0 = __ldg(&x4[(size_t)n0 * DIM4 + lane]);
            float4 w0 = __ldg(&rs4[(size_t)r0 * DIM4 + lane]);
            acc_term(acc0, v0, w0, a, b, ((int)y0 < 0) ? -1.f : 1.f);
        }
    }

    acc0.x += acc1.x + acc2.x + acc3.x;
    acc0.y += acc1.y + acc2.y + acc3.y;
    acc0.z += acc1.z + acc2.z + acc3.z;
    acc0.w += acc1.w + acc2.w + acc3.w;

    float inv = inv_du_of(n, heads[0], heads[2], rels[0], rels[2],
                          tails[0], tails[2]);
    acc0.x *= inv; acc0.y *= inv; acc0.z *= inv; acc0.w *= inv;
    reinterpret_cast<float4*>(out)[(size_t)n * DIM4 + lane] = acc0;
}

// ---------------------------------------------------------------------------
// Launch
// ---------------------------------------------------------------------------
extern "C" void kernel_launch(void* const* d_in, const int* in_sizes, int n_in,
                              void* d_out, int out_size) {
    const float* x      = (const float*)d_in[0];
    const float* r      = (const float*)d_in[1];
    const float* gamma  = (const float*)d_in[2];
    const float* beta   = (const float*)d_in[3];
    const float* kern   = (const float*)d_in[4];
    const int* edges    = (const int*)d_in[5];
    const int* rels     = (const int*)d_in[6];

    int e = in_sizes[0] / DIM;           // 50000
    int rsc_total = in_sizes[1];         // n_rels * DIM
    int E = in_sizes[6];                 // 625000
    const int* heads = edges;
    const int* tails = edges + E;
    float* out = (float*)d_out;

    // Adjacency build (packed 4-byte entries, no scan)
    k_zero<<<(e + 255) / 256, 256>>>(e);
    k_fill<<<(E + 255) / 256, 256>>>(heads, tails, rels, E);

    // BN prep
    k_stats<<<NSTATB, DIM>>>(x, e);
    k_coef<<<DIM, 256>>>(gamma, beta, kern, e);
    k_rsc<<<(rsc_total + 255) / 256, 256>>>(r, kern, rsc_total);

    // Pull-gather: one warp per node, single write, no atomics
    k_gather<<<(e + 7) / 8, 256>>>(x, heads, tails, rels, out, e);
}

// round 13
// speedup vs baseline: 1.0454x; 1.0454x over previous
#include <cuda_runtime.h>

#define DIM 128
#define DIM4 (DIM / 4)          // 32 float4 per row
#define NODES_MAX 50000
#define NRELS_MAX 1000
#define PAD 96                  // max combined degree (Poisson(25); >=8 sigma)
#define NSTATB 1024
#define BN_EPS 1e-5f
#define OUTF 0x80000000u        // out-edge flag in rel field

// Scratch (static device globals — allowed; no runtime allocation)
__device__ float g_rsc[NRELS_MAX * DIM];       // r * kernels
__device__ float g_psum[DIM * NSTATB];         // transposed: [d][b]
__device__ float g_psq[DIM * NSTATB];
__device__ float g_ca[DIM];                    // fused affine scale
__device__ float g_cb[DIM];                    // fused affine shift
__device__ int   g_cnt[NODES_MAX];
__device__ int2  g_lst[NODES_MAX * PAD];       // (neighbor, rel|flag)

// ---------------------------------------------------------------------------
// inv_du from the reference's degenerate degree loop (6 scalars)
// ---------------------------------------------------------------------------
__device__ __forceinline__ float inv_du_of(int n, int h0, int h2, int r0,
                                           int r2, int t0, int t2) {
    float du = 1.f;
    if (h0 != h2) du += (float)((n == h0) + (n == h2));
    if (r0 != r2) du += (float)((n == r0) + (n == r2));
    if (t0 != t2) du += (float)((n == t0) + (n == t2));
    return 1.0f / du;
}

// ---------------------------------------------------------------------------
// K1: per-block partial column sums (reads coalesced; 2 scattered stores)
// ---------------------------------------------------------------------------
__global__ void k_stats(const float* __restrict__ x, int e) {
    int d = threadIdx.x;            // 0..127
    int b = blockIdx.x;             // 0..NSTATB-1
    float s = 0.f, ss = 0.f;
    for (int row = b; row < e; row += NSTATB) {
        float v = x[(size_t)row * DIM + d];
        s += v;
        ss += v * v;
    }
    g_psum[d * NSTATB + b] = s;
    g_psq[d * NSTATB + b] = ss;
}

// ---------------------------------------------------------------------------
// K2: parallel reduce, coalesced reads (thread t reads [d*NSTATB + t])
// ---------------------------------------------------------------------------
__global__ void __launch_bounds__(256) k_coef(
        const float* __restrict__ gamma,
        const float* __restrict__ beta,
        const float* __restrict__ kern, int e) {
    __shared__ double sh_s[256];
    __shared__ double sh_q[256];
    int d = blockIdx.x;             // 0..127 feature index
    int t = threadIdx.x;            // 0..255

    double s = 0.0, ss = 0.0;
    #pragma unroll
    for (int b = t; b < NSTATB; b += 256) {
        s  += (double)g_psum[d * NSTATB + b];
        ss += (double)g_psq[d * NSTATB + b];
    }
    sh_s[t] = s;
    sh_q[t] = ss;
    __syncthreads();
    for (int o = 128; o > 0; o >>= 1) {
        if (t < o) {
            sh_s[t] += sh_s[t + o];
            sh_q[t] += sh_q[t + o];
        }
        __syncthreads();
    }
    if (t == 0) {
        double mean_d = sh_s[0] / (double)e;
        double var_d  = sh_q[0] / (double)e - mean_d * mean_d;  // biased var
        float mean = (float)mean_d;
        float inv = rsqrtf((float)var_d + BN_EPS);
        float g = gamma[d], k = kern[d];
        g_ca[d] = inv * g * k;
        g_cb[d] = (beta[d] - mean * inv * g) * k;
    }
}

// ---------------------------------------------------------------------------
// K3: r * kernels
// ---------------------------------------------------------------------------
__global__ void k_rsc(const float* __restrict__ r,
                      const float* __restrict__ kern, int total) {
    int i = blockIdx.x * blockDim.x + threadIdx.x;
    if (i < total) g_rsc[i] = r[i] * kern[i & (DIM - 1)];
}

// ---------------------------------------------------------------------------
// Adjacency build: zero counters, then single-pass padded-bucket fill.
// ONE combined list per node: in-edge (neighbor=head, rel), out-edge
// (neighbor=tail, rel|OUTF -> subtract rsc).
// ---------------------------------------------------------------------------
__global__ void k_zero(int e) {
    int i = blockIdx.x * blockDim.x + threadIdx.x;
    if (i < e) g_cnt[i] = 0;
}

__global__ void k_fill(const int* __restrict__ heads,
                       const int* __restrict__ tails,
                       const int* __restrict__ rels, int E) {
    int i = blockIdx.x * blockDim.x + threadIdx.x;
    if (i >= E) return;
    int h = heads[i], t = tails[i], rl = rels[i];
    int p = atomicAdd(&g_cnt[t], 1);
    if (p < PAD) g_lst[t * PAD + p] = make_int2(h, rl);             // in-edge
    int q = atomicAdd(&g_cnt[h], 1);
    if (q < PAD) g_lst[h * PAD + q] = make_int2(t, (int)(rl | OUTF)); // out
}

// ---------------------------------------------------------------------------
// acc += (v*a + b) + sgn * w
// ---------------------------------------------------------------------------
__device__ __forceinline__ void acc_term(float4& acc, float4 v, float4 w,
                                         float4 a, float4 b, float sgn) {
    acc.x += fmaf(sgn, w.x, fmaf(v.x, a.x, b.x));
    acc.y += fmaf(sgn, w.y, fmaf(v.y, a.y, b.y));
    acc.z += fmaf(sgn, w.z, fmaf(v.z, a.z, b.z));
    acc.w += fmaf(sgn, w.w, fmaf(v.w, a.w, b.w));
}

// ---------------------------------------------------------------------------
// K4: pull-gather over the combined list. One warp per node; 4-deep
// unrolled gathers, one deterministic STG per row.
// ---------------------------------------------------------------------------
__global__ void __launch_bounds__(256) k_gather(
        const float* __restrict__ x,
        const int* __restrict__ heads,
        const int* __restrict__ tails,
        const int* __restrict__ rels,
        float* __restrict__ out, int e) {
    int n = (blockIdx.x * blockDim.x + threadIdx.x) >> 5;
    if (n >= e) return;
    int lane = threadIdx.x & 31;

    const float4* x4  = reinterpret_cast<const float4*>(x);
    const float4* rs4 = reinterpret_cast<const float4*>(g_rsc);
    float4 a = reinterpret_cast<const float4*>(g_ca)[lane];
    float4 b = reinterpret_cast<const float4*>(g_cb)[lane];

    // seed: own normalized row
    float4 v = x4[(size_t)n * DIM4 + lane];
    float4 acc0, acc1, acc2, acc3;
    acc0.x = fmaf(v.x, a.x, b.x);
    acc0.y = fmaf(v.y, a.y, b.y);
    acc0.z = fmaf(v.z, a.z, b.z);
    acc0.w = fmaf(v.w, a.w, b.w);
    acc1 = make_float4(0.f, 0.f, 0.f, 0.f);
    acc2 = acc1; acc3 = acc1;

    int cnt = min(g_cnt[n], PAD);
    const int2* list = g_lst + (size_t)n * PAD;

    for (int base = 0; base < cnt; base += 32) {
        int idx = base + lane;
        int2 pr = (idx < cnt) ? list[idx] : make_int2(0, 0);
        int m = min(32, cnt - base);
        int j = 0;
        for (; j + 3 < m; j += 4) {
            int n0 = __shfl_sync(0xffffffffu, pr.x, j);
            int y0 = __shfl_sync(0xffffffffu, pr.y, j);
            int n1 = __shfl_sync(0xffffffffu, pr.x, j + 1);
            int y1 = __shfl_sync(0xffffffffu, pr.y, j + 1);
            int n2 = __shfl_sync(0xffffffffu, pr.x, j + 2);
            int y2 = __shfl_sync(0xffffffffu, pr.y, j + 2);
            int n3 = __shfl_sync(0xffffffffu, pr.x, j + 3);
            int y3 = __shfl_sync(0xffffffffu, pr.y, j + 3);
            int r0 = y0 & 0x7fffffff, r1 = y1 & 0x7fffffff;
            int r2 = y2 & 0x7fffffff, r3 = y3 & 0x7fffffff;
            // 8 independent 16B loads in flight
            float4 v0 = __ldg(&x4[(size_t)n0 * DIM4 + lane]);
            float4 v1 = __ldg(&x4[(size_t)n1 * DIM4 + lane]);
            float4 v2 = __ldg(&x4[(size_t)n2 * DIM4 + lane]);
            float4 v3 = __ldg(&x4[(size_t)n3 * DIM4 + lane]);
            float4 w0 = __ldg(&rs4[(size_t)r0 * DIM4 + lane]);
            float4 w1 = __ldg(&rs4[(size_t)r1 * DIM4 + lane]);
            float4 w2 = __ldg(&rs4[(size_t)r2 * DIM4 + lane]);
            float4 w3 = __ldg(&rs4[(size_t)r3 * DIM4 + lane]);
            acc_term(acc0, v0, w0, a, b, (y0 < 0) ? -1.f : 1.f);
            acc_term(acc1, v1, w1, a, b, (y1 < 0) ? -1.f : 1.f);
            acc_term(acc2, v2, w2, a, b, (y2 < 0) ? -1.f : 1.f);
            acc_term(acc3, v3, w3, a, b, (y3 < 0) ? -1.f : 1.f);
        }
        for (; j < m; j++) {
            int n0 = __shfl_sync(0xffffffffu, pr.x, j);
            int y0 = __shfl_sync(0xffffffffu, pr.y, j);
            int r0 = y0 & 0x7fffffff;
            float4 v0 = __ldg(&x4[(size_t)n0 * DIM4 + lane]);
            float4 w0 = __ldg(&rs4[(size_t)r0 * DIM4 + lane]);
            acc_term(acc0, v0, w0, a, b, (y0 < 0) ? -1.f : 1.f);
        }
    }

    acc0.x += acc1.x + acc2.x + acc3.x;
    acc0.y += acc1.y + acc2.y + acc3.y;
    acc0.z += acc1.z + acc2.z + acc3.z;
    acc0.w += acc1.w + acc2.w + acc3.w;

    float inv = inv_du_of(n, heads[0], heads[2], rels[0], rels[2],
                          tails[0], tails[2]);
    acc0.x *= inv; acc0.y *= inv; acc0.z *= inv; acc0.w *= inv;
    reinterpret_cast<float4*>(out)[(size_t)n * DIM4 + lane] = acc0;
}

// ---------------------------------------------------------------------------
// Launch: fork the adjacency build onto a side stream so it overlaps the
// BN-prep chain inside the captured graph; join before the gather.
// (Streams/events are host objects, not device memory; created per call —
// kernel_launch only runs during correctness check + capture.)
// ---------------------------------------------------------------------------
extern "C" void kernel_launch(void* const* d_in, const int* in_sizes, int n_in,
                              void* d_out, int out_size) {
    const float* x      = (const float*)d_in[0];
    const float* r      = (const float*)d_in[1];
    const float* gamma  = (const float*)d_in[2];
    const float* beta   = (const float*)d_in[3];
    const float* kern   = (const float*)d_in[4];
    const int* edges    = (const int*)d_in[5];
    const int* rels     = (const int*)d_in[6];

    int e = in_sizes[0] / DIM;           // 50000
    int rsc_total = in_sizes[1];         // n_rels * DIM
    int E = in_sizes[6];                 // 625000
    const int* heads = edges;
    const int* tails = edges + E;
    float* out = (float*)d_out;

    cudaStream_t s2;
    cudaStreamCreateWithFlags(&s2, cudaStreamNonBlocking);
    cudaEvent_t evFork, evJoin;
    cudaEventCreateWithFlags(&evFork, cudaEventDisableTiming);
    cudaEventCreateWithFlags(&evJoin, cudaEventDisableTiming);

    // Fork: side stream joins the capture via the event dependency.
    cudaEventRecord(evFork, 0);
    cudaStreamWaitEvent(s2, evFork, 0);

    // Branch A (side stream): adjacency build
    k_zero<<<(e + 255) / 256, 256, 0, s2>>>(e);
    k_fill<<<(E + 255) / 256, 256, 0, s2>>>(heads, tails, rels, E);

    // Branch B (main stream): BN prep
    k_stats<<<NSTATB, DIM>>>(x, e);
    k_coef<<<DIM, 256>>>(gamma, beta, kern, e);
    k_rsc<<<(rsc_total + 255) / 256, 256>>>(r, kern, rsc_total);

    // Join: gather needs both branches.
    cudaEventRecord(evJoin, s2);
    cudaStreamWaitEvent(0, evJoin, 0);

    k_gather<<<(e + 7) / 8, 256>>>(x, heads, tails, rels, out, e);
}